// round 10
// baseline (speedup 1.0000x reference)
#include <cuda_runtime.h>
#include <cuda_fp16.h>
#include <mma.h>
using namespace nvcuda;

// Problem constants
#define NN 50000
#define EE 800000
#define K_CHEB 16
#define BN_EPS 1e-5f

// ---------------- scratch (device globals; no allocation allowed) ----------------
__device__ int   g_is64;
__device__ int   g_deg[NN];
__device__ float g_dinv[NN];
__device__ int   g_cnt[NN];
__device__ int   g_rowptr[NN + 1];
__device__ int   g_fill[NN];
__device__ int2  g_cw[EE];          // packed (src, weight-bits) per edge
__device__ int   g_bsum[64];
__device__ int   g_total[1];

// Big fp16 buffer: all 16 Chebyshev terms for layer 1 (slice 0 becomes h after BN)
__device__ __half g_big[(size_t)K_CHEB * NN * 128];       // 204.8 MB
// fp16 weights
__device__ __half g_W1h[16 * 128 * 128];
__device__ __half g_W2t[128 * 512];                       // W2t[f][k*32+c] = W2[k][f][c]
// layer outputs
__device__ float g_out1[(size_t)NN * 128];
__device__ float g_out2[(size_t)NN * 32];
__device__ float g_stats[2 * 128];
// Layer-2 Clenshaw: P[k][N][32] fp32, B chain fp32 + fp16 gather mirrors
__device__ float  g_P[(size_t)16 * NN * 32];              // 102.4 MB
__device__ float  g_Bf[3][(size_t)NN * 32];
__device__ __half g_Bh[3][(size_t)NN * 32];

// float buffers: 0=out1 1=out2
__device__ __forceinline__ float* fbuf(int i) {
    return (i == 0) ? g_out1 : g_out2;
}

// ---------------- edge dtype detection ----------------

__global__ void detect_k(const int* __restrict__ ei32) {
    int e = blockIdx.x * blockDim.x + threadIdx.x;
    if (e >= 4096) return;
    if (ei32[2 * e + 1] != 0) g_is64 = 0;
}

__device__ __forceinline__ void load_edge(const int* __restrict__ ei32, int e,
                                          int& s, int& d) {
    if (g_is64) { s = ei32[2 * e]; d = ei32[2 * (EE + e)]; }
    else        { s = ei32[e];     d = ei32[EE + e]; }
}

// ---------------- zero-init (also seeds g_is64 = 1) ----------------

__global__ void zero_graph_k() {
    int i = blockIdx.x * blockDim.x + threadIdx.x;
    if (i == 0) g_is64 = 1;
    if (i < NN) { g_deg[i] = 0; g_cnt[i] = 0; }
}

__global__ void zero_stats_k() {
    int i = threadIdx.x;
    if (i < 2 * 128) g_stats[i] = 0.f;
}

// ---------------- graph preprocessing ----------------

__global__ void deg_count_k(const int* __restrict__ ei32) {
    int e = blockIdx.x * blockDim.x + threadIdx.x;
    if (e >= EE) return;
    int s, d;
    load_edge(ei32, e, s, d);
    if ((unsigned)s >= NN || (unsigned)d >= NN) return;
    if (s != d) { atomicAdd(&g_deg[s], 1); atomicAdd(&g_cnt[d], 1); }
}

__global__ void dinv_k() {
    int i = blockIdx.x * blockDim.x + threadIdx.x;
    if (i >= NN) return;
    int d = g_deg[i];
    g_dinv[i] = (d > 0) ? rsqrtf((float)d) : 0.0f;
}

__global__ void scan_block_k() {
    __shared__ int sh[1024];
    int i = blockIdx.x * 1024 + threadIdx.x;
    int v = (i < NN) ? g_cnt[i] : 0;
    sh[threadIdx.x] = v;
    __syncthreads();
    for (int off = 1; off < 1024; off <<= 1) {
        int t = (threadIdx.x >= off) ? sh[threadIdx.x - off] : 0;
        __syncthreads();
        sh[threadIdx.x] += t;
        __syncthreads();
    }
    if (i < NN) g_rowptr[i] = sh[threadIdx.x] - v;
    if (threadIdx.x == 1023) g_bsum[blockIdx.x] = sh[1023];
}

__global__ void scan_top_k(int nb) {
    if (threadIdx.x == 0) {
        int run = 0;
        for (int b = 0; b < nb; b++) { int t = g_bsum[b]; g_bsum[b] = run; run += t; }
        g_total[0] = run;
    }
}

__global__ void scan_add_k() {
    int i = blockIdx.x * blockDim.x + threadIdx.x;
    if (i < NN) {
        int v = g_rowptr[i] + g_bsum[i >> 10];
        g_rowptr[i] = v;
        g_fill[i] = v;
    }
    if (i == NN) g_rowptr[NN] = g_total[0];
}

__global__ void scatter_k(const int* __restrict__ ei32) {
    int e = blockIdx.x * blockDim.x + threadIdx.x;
    if (e >= EE) return;
    int s, d;
    load_edge(ei32, e, s, d);
    if ((unsigned)s >= NN || (unsigned)d >= NN) return;
    if (s == d) return;
    int pos = atomicAdd(&g_fill[d], 1);
    float w = -g_dinv[s] * g_dinv[d];
    g_cw[pos] = make_int2(s, __float_as_int(w));
}

// ---------------- conversions ----------------

__global__ void conv_x_k(const float* __restrict__ x) {   // x -> slice 0 fp16
    int i = blockIdx.x * blockDim.x + threadIdx.x;
    if (i < NN * 128) g_big[i] = __float2half(x[i]);
}

__global__ void conv_w_k(const float* __restrict__ W1, const float* __restrict__ W2) {
    int i = blockIdx.x * blockDim.x + threadIdx.x;
    if (i < 16 * 128 * 128) g_W1h[i] = __float2half(W1[i]);
    if (i < 128 * 512) {
        int f = i >> 9, j = i & 511;
        g_W2t[i] = __float2half(W2[(j >> 5) * 128 * 32 + f * 32 + (j & 31)]);
    }
}

// ------- layer-1 propagation (width 128, warp per row, fp16 slices only) -------

__global__ void prop_first_s(int x_slice, int y_slice) {
    const __half* __restrict__ X = g_big + (size_t)x_slice * NN * 128;
    __half* __restrict__ Yh = g_big + (size_t)y_slice * NN * 128;
    int wid = (blockIdx.x * blockDim.x + threadIdx.x) >> 5;
    int lane = threadIdx.x & 31;
    if (wid >= NN) return;
    int beg = g_rowptr[wid], end = g_rowptr[wid + 1];
    float ax = 0.f, ay = 0.f, az = 0.f, aw = 0.f;
#pragma unroll 8
    for (int e = beg; e < end; e++) {
        int2 cw = __ldg(&g_cw[e]);
        float w = __int_as_float(cw.y);
        uint2 u = __ldg(((const uint2*)(X + (size_t)cw.x * 128)) + lane);
        float2 f0 = __half22float2(*(__half2*)&u.x);
        float2 f1 = __half22float2(*(__half2*)&u.y);
        ax = fmaf(w, f0.x, ax);
        ay = fmaf(w, f0.y, ay);
        az = fmaf(w, f1.x, az);
        aw = fmaf(w, f1.y, aw);
    }
    uint2 o;
    *(__half2*)&o.x = __floats2half2_rn(ax, ay);
    *(__half2*)&o.y = __floats2half2_rn(az, aw);
    ((uint2*)(Yh + (size_t)wid * 128))[lane] = o;
}

// Tx_k = 2 L Tx_{k-1} - Tx_{k-2}
__global__ void prop_rec_s(int x1_slice, int x0_slice, int y_slice) {
    const __half* __restrict__ X1 = g_big + (size_t)x1_slice * NN * 128;
    const __half* __restrict__ X0 = g_big + (size_t)x0_slice * NN * 128;
    __half* __restrict__ Yh = g_big + (size_t)y_slice * NN * 128;
    int wid = (blockIdx.x * blockDim.x + threadIdx.x) >> 5;
    int lane = threadIdx.x & 31;
    if (wid >= NN) return;
    int beg = g_rowptr[wid], end = g_rowptr[wid + 1];
    float ax = 0.f, ay = 0.f, az = 0.f, aw = 0.f;
#pragma unroll 8
    for (int e = beg; e < end; e++) {
        int2 cw = __ldg(&g_cw[e]);
        float w = __int_as_float(cw.y);
        uint2 u = __ldg(((const uint2*)(X1 + (size_t)cw.x * 128)) + lane);
        float2 f0 = __half22float2(*(__half2*)&u.x);
        float2 f1 = __half22float2(*(__half2*)&u.y);
        ax = fmaf(w, f0.x, ax);
        ay = fmaf(w, f0.y, ay);
        az = fmaf(w, f1.x, az);
        aw = fmaf(w, f1.y, aw);
    }
    uint2 p = ((const uint2*)(X0 + (size_t)wid * 128))[lane];
    float2 p0 = __half22float2(*(__half2*)&p.x);
    float2 p1 = __half22float2(*(__half2*)&p.y);
    uint2 o;
    *(__half2*)&o.x = __floats2half2_rn(2.f * ax - p0.x, 2.f * ay - p0.y);
    *(__half2*)&o.y = __floats2half2_rn(2.f * az - p1.x, 2.f * aw - p1.y);
    ((uint2*)(Yh + (size_t)wid * 128))[lane] = o;
}

// ---------------- layer-1 fused tensor-core GEMM (K = 2048) ----------------

__global__ void gemm_tc128_k(int n) {
    const int warp = threadIdx.x >> 5;
    const int row0 = blockIdx.x * 128 + warp * 16;
    __shared__ __align__(32) __half Bs[16 * 128];
    wmma::fragment<wmma::accumulator, 16, 16, 16, float> acc[8];
#pragma unroll
    for (int i = 0; i < 8; i++) wmma::fill_fragment(acc[i], 0.f);

    for (int kc = 0; kc < 128; kc++) {
        ((uint4*)Bs)[threadIdx.x] = ((const uint4*)(g_W1h + (size_t)kc * 16 * 128))[threadIdx.x];
        __syncthreads();
        if (row0 < n) {
            int slice = kc >> 3;
            int f0 = (kc & 7) * 16;
            const __half* Ag = g_big + (size_t)slice * NN * 128 + (size_t)row0 * 128 + f0;
            wmma::fragment<wmma::matrix_a, 16, 16, 16, __half, wmma::row_major> a;
            wmma::load_matrix_sync(a, Ag, 128);
#pragma unroll
            for (int nf = 0; nf < 8; nf++) {
                wmma::fragment<wmma::matrix_b, 16, 16, 16, __half, wmma::row_major> b;
                wmma::load_matrix_sync(b, Bs + nf * 16, 128);
                wmma::mma_sync(acc[nf], a, b, acc[nf]);
            }
        }
        __syncthreads();
    }
    if (row0 < n) {
#pragma unroll
        for (int nf = 0; nf < 8; nf++)
            wmma::store_matrix_sync(g_out1 + (size_t)row0 * 128 + nf * 16, acc[nf],
                                    128, wmma::mem_row_major);
    }
}

// ---------------- layer-2: P = h * W2 (all 16 taps), P[k][N][32] ----------------

__global__ void gemm_P_k(int n) {
    const int warp = threadIdx.x >> 5;
    const int row0 = blockIdx.x * 128 + warp * 16;
    const int jb = blockIdx.y;
    __shared__ __align__(32) __half Bs[16 * 128];
    wmma::fragment<wmma::accumulator, 16, 16, 16, float> acc[8];
#pragma unroll
    for (int i = 0; i < 8; i++) wmma::fill_fragment(acc[i], 0.f);

    for (int kc = 0; kc < 8; kc++) {
        int t = threadIdx.x >> 4, u = threadIdx.x & 15;
        ((uint4*)Bs)[threadIdx.x] =
            *(const uint4*)(g_W2t + (size_t)(kc * 16 + t) * 512 + jb * 128 + u * 8);
        __syncthreads();
        if (row0 < n) {
            const __half* Ag = g_big + (size_t)row0 * 128 + kc * 16;
            wmma::fragment<wmma::matrix_a, 16, 16, 16, __half, wmma::row_major> a;
            wmma::load_matrix_sync(a, Ag, 128);
#pragma unroll
            for (int nf = 0; nf < 8; nf++) {
                wmma::fragment<wmma::matrix_b, 16, 16, 16, __half, wmma::row_major> b;
                wmma::load_matrix_sync(b, Bs + nf * 16, 128);
                wmma::mma_sync(acc[nf], a, b, acc[nf]);
            }
        }
        __syncthreads();
    }
    if (row0 < n) {
#pragma unroll
        for (int nf = 0; nf < 8; nf++) {
            int j0 = jb * 128 + nf * 16;
            wmma::store_matrix_sync(g_P + (size_t)(j0 >> 5) * NN * 32 +
                                        (size_t)row0 * 32 + (j0 & 31),
                                    acc[nf], 32, wmma::mem_row_major);
        }
    }
}

// B_15 = P_15
__global__ void p_copy_k(int b_idx) {
    int i = blockIdx.x * blockDim.x + threadIdx.x;
    if (i >= NN * 32) return;
    float v = g_P[(size_t)15 * NN * 32 + i];
    g_Bf[b_idx][i] = v;
    g_Bh[b_idx][i] = __float2half(v);
}

// Clenshaw step, 4 rows per warp. Bout = 2*L*B1 - B2 + P_k
__global__ void clen_step_k(int b1, int b2, int pk, int outb) {
    int t = blockIdx.x * blockDim.x + threadIdx.x;
    int row = t >> 3;
    int sl = t & 7;
    if (row >= NN) return;
    const __half* __restrict__ B1h = g_Bh[b1];
    int beg = g_rowptr[row], end = g_rowptr[row + 1];
    float a0 = 0.f, a1 = 0.f, a2 = 0.f, a3 = 0.f;
#pragma unroll 8
    for (int e = beg; e < end; e++) {
        int2 cw = __ldg(&g_cw[e]);
        float w = __int_as_float(cw.y);
        uint2 u = __ldg(((const uint2*)(B1h + (size_t)cw.x * 32)) + sl);
        float2 f0 = __half22float2(*(__half2*)&u.x);
        float2 f1 = __half22float2(*(__half2*)&u.y);
        a0 = fmaf(w, f0.x, a0);
        a1 = fmaf(w, f0.y, a1);
        a2 = fmaf(w, f1.x, a2);
        a3 = fmaf(w, f1.y, a3);
    }
    size_t idx = (size_t)row * 32 + sl * 4;
    float4 x0 = (b2 >= 0) ? *(const float4*)&g_Bf[b2][idx]
                          : make_float4(0.f, 0.f, 0.f, 0.f);
    float4 pv = *(const float4*)&g_P[(size_t)pk * NN * 32 + idx];
    float4 v;
    v.x = 2.f * a0 - x0.x + pv.x;
    v.y = 2.f * a1 - x0.y + pv.y;
    v.z = 2.f * a2 - x0.z + pv.z;
    v.w = 2.f * a3 - x0.w + pv.w;
    *(float4*)&g_Bf[outb][idx] = v;
    uint2 o;
    *(__half2*)&o.x = __floats2half2_rn(v.x, v.y);
    *(__half2*)&o.y = __floats2half2_rn(v.z, v.w);
    *(uint2*)&g_Bh[outb][idx] = o;
}

// Final: out2 = L*B1 - B2 + P_0
__global__ void clen_final_k(int b1, int b2) {
    int t = blockIdx.x * blockDim.x + threadIdx.x;
    int row = t >> 3;
    int sl = t & 7;
    if (row >= NN) return;
    const __half* __restrict__ B1h = g_Bh[b1];
    int beg = g_rowptr[row], end = g_rowptr[row + 1];
    float a0 = 0.f, a1 = 0.f, a2 = 0.f, a3 = 0.f;
#pragma unroll 8
    for (int e = beg; e < end; e++) {
        int2 cw = __ldg(&g_cw[e]);
        float w = __int_as_float(cw.y);
        uint2 u = __ldg(((const uint2*)(B1h + (size_t)cw.x * 32)) + sl);
        float2 f0 = __half22float2(*(__half2*)&u.x);
        float2 f1 = __half22float2(*(__half2*)&u.y);
        a0 = fmaf(w, f0.x, a0);
        a1 = fmaf(w, f0.y, a1);
        a2 = fmaf(w, f1.x, a2);
        a3 = fmaf(w, f1.y, a3);
    }
    size_t idx = (size_t)row * 32 + sl * 4;
    float4 x0 = *(const float4*)&g_Bf[b2][idx];
    float4 pv = *(const float4*)&g_P[idx];
    float4 v;
    v.x = a0 - x0.x + pv.x;
    v.y = a1 - x0.y + pv.y;
    v.z = a2 - x0.z + pv.z;
    v.w = a3 - x0.w + pv.w;
    *(float4*)&g_out2[idx] = v;
}

// ---------------- BatchNorm (training-mode) + ReLU ----------------

__global__ void bn_stats_k(int v_f, int total, int F) {
    const float* __restrict__ V = fbuf(v_f);
    int idx = blockIdx.x * blockDim.x + threadIdx.x;
    int stride = gridDim.x * blockDim.x;
    float s = 0.f, s2 = 0.f;
    int col = idx % F;
    for (int i = idx; i < total; i += stride) {
        float v = V[i];
        s += v;
        s2 = fmaf(v, v, s2);
    }
    atomicAdd(&g_stats[col], s);
    atomicAdd(&g_stats[F + col], s2);
}

__global__ void bn_finalize_k(const float* __restrict__ gamma,
                              const float* __restrict__ beta, int F, float invN) {
    int c = threadIdx.x;
    if (c < F) {
        float mu = g_stats[c] * invN;
        float var = g_stats[F + c] * invN - mu * mu;
        float sc = gamma[c] * rsqrtf(var + BN_EPS);
        g_stats[c] = sc;
        g_stats[F + c] = beta[c] - sc * mu;
    }
}

__global__ void bn_apply_k(int v_f, float* __restrict__ Yext, int write_ext,
                           int yh_slice, int total, int F) {
    const float* __restrict__ V = fbuf(v_f);
    int idx = blockIdx.x * blockDim.x + threadIdx.x;
    if (idx >= total) return;
    int c = idx % F;
    float y = fmaf(g_stats[c], V[idx], g_stats[F + c]);
    y = fmaxf(y, 0.f);
    if (write_ext) Yext[idx] = y;
    if (yh_slice >= 0) g_big[(size_t)yh_slice * NN * 128 + idx] = __float2half(y);
}

// ---------------- host launch: kernel launches ONLY ----------------

extern "C" void kernel_launch(void* const* d_in, const int* in_sizes, int n_in,
                              void* d_out, int out_size) {
    const float* x  = (const float*)d_in[0];
    const int* ei32 = (const int*)d_in[1];
    const float* W1 = (const float*)d_in[2];
    const float* W2 = (const float*)d_in[4];
    const float* g1 = (const float*)d_in[6];
    const float* be1 = (const float*)d_in[7];
    const float* g2 = (const float*)d_in[8];
    const float* be2 = (const float*)d_in[9];
    float* out = (float*)d_out;

    const int FO1 = 0, FO2 = 1;

    // --- preprocessing ---
    zero_graph_k<<<(NN + 255) / 256, 256>>>();     // also seeds g_is64 = 1
    detect_k<<<16, 256>>>(ei32);
    deg_count_k<<<(EE + 255) / 256, 256>>>(ei32);
    dinv_k<<<(NN + 255) / 256, 256>>>();
    int nb = (NN + 1023) / 1024;
    scan_block_k<<<nb, 1024>>>();
    scan_top_k<<<1, 32>>>(nb);
    scan_add_k<<<(NN + 1 + 255) / 256, 256>>>();
    scatter_k<<<(EE + 255) / 256, 256>>>(ei32);
    conv_w_k<<<(16 * 128 * 128 + 255) / 256, 256>>>(W1, W2);

    const int PROP_GRID = (NN * 32 + 511) / 512;     // warp per row, 512-thr blocks
    const int CLEN_GRID = (NN * 8 + 255) / 256;      // 8 threads per row
    const int GT = (NN + 127) / 128;

    // --- layer 1: ChebConv(128 -> 128), fp16 slice recurrence + fused GEMM ---
    conv_x_k<<<(NN * 128 + 255) / 256, 256>>>(x);
    prop_first_s<<<PROP_GRID, 512>>>(0, 1);
    for (int k = 2; k < K_CHEB; k++)
        prop_rec_s<<<PROP_GRID, 512>>>(k - 1, k - 2, k);
    gemm_tc128_k<<<GT, 256>>>(NN);
    zero_stats_k<<<1, 256>>>();
    bn_stats_k<<<256, 256>>>(FO1, NN * 128, 128);
    bn_finalize_k<<<1, 128>>>(g1, be1, 128, 1.0f / NN);
    bn_apply_k<<<(NN * 128 + 255) / 256, 256>>>(FO1, nullptr, 0, 0, NN * 128, 128);

    // --- layer 2: ChebConv(128 -> 32) via Clenshaw on width-32 operands ---
    {
        dim3 gp(GT, 4);
        gemm_P_k<<<gp, 256>>>(NN);
    }
    p_copy_k<<<(NN * 32 + 255) / 256, 256>>>(0);
    clen_step_k<<<CLEN_GRID, 256>>>(0, -1, 14, 1);
    {
        int prev = 0, cur = 1, fre = 2;
        for (int k = 13; k >= 1; k--) {
            clen_step_k<<<CLEN_GRID, 256>>>(cur, prev, k, fre);
            int t = prev; prev = cur; cur = fre; fre = t;
        }
        clen_final_k<<<CLEN_GRID, 256>>>(cur, prev);
    }
    zero_stats_k<<<1, 256>>>();
    bn_stats_k<<<256, 256>>>(FO2, NN * 32, 32);
    bn_finalize_k<<<1, 32>>>(g2, be2, 32, 1.0f / NN);
    bn_apply_k<<<(NN * 32 + 255) / 256, 256>>>(FO2, out, 1, -1, NN * 32, 32);
}